// round 9
// baseline (speedup 1.0000x reference)
#include <cuda_runtime.h>
#include <cuda_bf16.h>

#define VSZ 32000
#define HSZ 256
#define BSZ 256
#define SSZ 512

typedef unsigned long long ull;

// Scratch (device globals; no allocation allowed)
__device__ float g_eproj[(size_t)VSZ * 768];   // emb @ [Wz;Wr;Wh]^T + biases
__device__ float g_hlast[BSZ * HSZ];
// Transposed packed bf16 U, k-grouped for uint4 loads:
//  g_zr4[k2][jg] = { z(2k2), r(2k2), z(2k2+1), r(2k2+1) }  (each = bf16x2 of cols 2jg,2jg+1)
//  g_uh4[k4][jg] = { h(4k4), h(4k4+1), h(4k4+2), h(4k4+3) }
__device__ uint4 g_zr4[128 * 128];
__device__ uint4 g_uh4[64 * 128];

// ---- packed f32x2 helpers (Blackwell sm_103a) ----
__device__ __forceinline__ ull pk2(float lo, float hi) {
    ull r;
    asm("mov.b64 %0, {%1, %2};" : "=l"(r) : "f"(lo), "f"(hi));
    return r;
}
__device__ __forceinline__ void fma2(ull& d, ull a, ull b) {
    asm("fma.rn.f32x2 %0, %1, %2, %0;" : "+l"(d) : "l"(a), "l"(b));
}
__device__ __forceinline__ ull addf2(ull a, ull b) {
    ull r;
    asm("add.rn.f32x2 %0, %1, %2;" : "=l"(r) : "l"(a), "l"(b));
    return r;
}
__device__ __forceinline__ ull bflyadd(ull v) {
    v = addf2(v, __shfl_xor_sync(0xffffffffu, v, 8));
    v = addf2(v, __shfl_xor_sync(0xffffffffu, v, 16));
    return v;
}
__device__ __forceinline__ float pick(ull v, int hi_sel) {
    float lo, hi;
    asm("mov.b64 {%0, %1}, %2;" : "=f"(lo), "=f"(hi) : "l"(v));
    return hi_sel ? hi : lo;
}
__device__ __forceinline__ ull bf2f2(unsigned v) {
    ull r;
    asm("{\n\t.reg .b32 lo, hi;\n\t"
        "shl.b32 lo, %1, 16;\n\t"
        "and.b32 hi, %1, 0xFFFF0000;\n\t"
        "mov.b64 %0, {lo, hi};\n\t}" : "=l"(r) : "r"(v));
    return r;
}
__device__ __forceinline__ float fast_sigm(float x) {
    float e, r;
    asm("ex2.approx.ftz.f32 %0, %1;" : "=f"(e) : "f"(-1.4426950408889634f * x));
    asm("rcp.approx.ftz.f32 %0, %1;" : "=f"(r) : "f"(1.0f + e));
    return r;
}
__device__ __forceinline__ float fast_tanh(float x) {
    float r;
    asm("tanh.approx.f32 %0, %1;" : "=f"(r) : "f"(x));
    return r;
}
__device__ __forceinline__ unsigned pkbf(float lo, float hi) {
    unsigned short l = __bfloat16_as_ushort(__float2bfloat16(lo));
    unsigned short h = __bfloat16_as_ushort(__float2bfloat16(hi));
    return ((unsigned)h << 16) | (unsigned)l;
}

// ============================================================================
// Pack U into transposed bf16 uint4 streams
// ============================================================================
__global__ void pack_u(const float* __restrict__ Uz, const float* __restrict__ Ur,
                       const float* __restrict__ Uh)
{
    const int k2 = blockIdx.x;     // 0..127
    const int jg = threadIdx.x;    // 0..127
    const int j0 = 2 * jg;
    const int ka = 2 * k2, kb = 2 * k2 + 1;
    uint4 v;
    v.x = pkbf(Uz[j0 * 256 + ka], Uz[(j0 + 1) * 256 + ka]);
    v.y = pkbf(Ur[j0 * 256 + ka], Ur[(j0 + 1) * 256 + ka]);
    v.z = pkbf(Uz[j0 * 256 + kb], Uz[(j0 + 1) * 256 + kb]);
    v.w = pkbf(Ur[j0 * 256 + kb], Ur[(j0 + 1) * 256 + kb]);
    g_zr4[k2 * 128 + jg] = v;
    if (k2 < 64) {
        const int kc = 4 * k2;
        uint4 h;
        h.x = pkbf(Uh[j0 * 256 + kc],     Uh[(j0 + 1) * 256 + kc]);
        h.y = pkbf(Uh[j0 * 256 + kc + 1], Uh[(j0 + 1) * 256 + kc + 1]);
        h.z = pkbf(Uh[j0 * 256 + kc + 2], Uh[(j0 + 1) * 256 + kc + 2]);
        h.w = pkbf(Uh[j0 * 256 + kc + 3], Uh[(j0 + 1) * 256 + kc + 3]);
        g_uh4[k2 * 128 + jg] = h;
    }
}

// ============================================================================
// SGEMM-NT with bias (~90% of scalar f32x2 floor)
// ============================================================================
__global__ void __launch_bounds__(256) sgemm_nt_bias(
    const float* __restrict__ A, const float* __restrict__ Bw,
    const float* __restrict__ bias1, const float* __restrict__ bias2,
    float* __restrict__ C, int ldc, int coloff)
{
    __shared__ __align__(16) float As[16][132];
    __shared__ __align__(16) float Bs[16][132];
    const int t  = threadIdx.x;
    const int tm = t >> 4;
    const int tn = t & 15;

    ull acc[8][4];
#pragma unroll
    for (int i = 0; i < 8; i++)
#pragma unroll
        for (int j = 0; j < 4; j++) acc[i][j] = 0ULL;

    const float* Ab = A  + (size_t)blockIdx.x * 128 * 256;
    const float* Bb = Bw + (size_t)blockIdx.y * 128 * 256;
    const int lr = t >> 2;
    const int lk = (t & 3) << 2;

    for (int k0 = 0; k0 < 256; k0 += 16) {
        float4 a0 = *(const float4*)(Ab + (size_t)lr * 256 + k0 + lk);
        float4 a1 = *(const float4*)(Ab + (size_t)(lr + 64) * 256 + k0 + lk);
        float4 b0 = *(const float4*)(Bb + (size_t)lr * 256 + k0 + lk);
        float4 b1 = *(const float4*)(Bb + (size_t)(lr + 64) * 256 + k0 + lk);
        __syncthreads();
        As[lk + 0][lr] = a0.x; As[lk + 1][lr] = a0.y;
        As[lk + 2][lr] = a0.z; As[lk + 3][lr] = a0.w;
        As[lk + 0][lr + 64] = a1.x; As[lk + 1][lr + 64] = a1.y;
        As[lk + 2][lr + 64] = a1.z; As[lk + 3][lr + 64] = a1.w;
        Bs[lk + 0][lr] = b0.x; Bs[lk + 1][lr] = b0.y;
        Bs[lk + 2][lr] = b0.z; Bs[lk + 3][lr] = b0.w;
        Bs[lk + 0][lr + 64] = b1.x; Bs[lk + 1][lr + 64] = b1.y;
        Bs[lk + 2][lr + 64] = b1.z; Bs[lk + 3][lr + 64] = b1.w;
        __syncthreads();
#pragma unroll
        for (int kk = 0; kk < 16; kk++) {
            float4 av0 = *(const float4*)(&As[kk][tm * 8]);
            float4 av1 = *(const float4*)(&As[kk][tm * 8 + 4]);
            const ull* bp = (const ull*)(&Bs[kk][tn * 8]);
            ull b2_0 = bp[0], b2_1 = bp[1], b2_2 = bp[2], b2_3 = bp[3];
            float av[8] = {av0.x, av0.y, av0.z, av0.w, av1.x, av1.y, av1.z, av1.w};
#pragma unroll
            for (int i = 0; i < 8; i++) {
                ull a2 = pk2(av[i], av[i]);
                fma2(acc[i][0], a2, b2_0);
                fma2(acc[i][1], a2, b2_1);
                fma2(acc[i][2], a2, b2_2);
                fma2(acc[i][3], a2, b2_3);
            }
        }
    }

    const int row0 = blockIdx.x * 128 + tm * 8;
    const int col0 = blockIdx.y * 128 + tn * 8;
#pragma unroll
    for (int i = 0; i < 8; i++) {
#pragma unroll
        for (int j = 0; j < 4; j++) {
            float lo, hi;
            asm("mov.b64 {%0, %1}, %2;" : "=f"(lo), "=f"(hi) : "l"(acc[i][j]));
            int n0 = col0 + j * 2;
            float e0 = bias1[n0]     + (bias2 ? bias2[n0]     : 0.0f);
            float e1 = bias1[n0 + 1] + (bias2 ? bias2[n0 + 1] : 0.0f);
            C[(size_t)(row0 + i) * ldc + coloff + n0]     = lo + e0;
            C[(size_t)(row0 + i) * ldc + coloff + n0 + 1] = hi + e1;
        }
    }
}

// ============================================================================
// GRU scan v9: 128 CTAs x 2 batch rows x 512 threads.
// Same warp-butterfly structure as v8, but U pinned BY K-HALVES (first half
// of every kh-quarter's k-range, ALL columns): every warp runs 16 LDS iters
// + 16 LDG iters (8+8 in phase 2), each sub-loop address-space uniform.
// All 16 warps have identical instruction streams -> no barrier skew.
// ============================================================================
#define SCAN_SM_BYTES 204928

// phase-1 fma body for one uint4 (2 k-pairs) at k-pair index kk within chunk
#define P1BODY(u, hb, kk)                                                   \
    {                                                                       \
        ull uz0 = bf2f2((u).x), ur0 = bf2f2((u).y);                         \
        ull uz1 = bf2f2((u).z), ur1 = bf2f2((u).w);                         \
        ulonglong2 h0 = *(const ulonglong2*)(hdup + (hb) + 4 * (kk));       \
        ulonglong2 h1 = *(const ulonglong2*)(hdup + (hb) + 4 * (kk) + 2);   \
        fma2(az0, uz0, h0.x); fma2(az1, uz0, h0.y);                         \
        fma2(ar0, ur0, h0.x); fma2(ar1, ur0, h0.y);                         \
        fma2(az0, uz1, h1.x); fma2(az1, uz1, h1.y);                         \
        fma2(ar0, ur1, h1.x); fma2(ar1, ur1, h1.y);                         \
    }

// phase-2 fma body for one uint4 (4 k) at k4 index kk within chunk
#define P2BODY(u, sb, kk)                                                   \
    {                                                                       \
        ull uh0 = bf2f2((u).x), uh1 = bf2f2((u).y);                         \
        ull uh2 = bf2f2((u).z), uh3 = bf2f2((u).w);                         \
        ulonglong2 s0 = *(const ulonglong2*)(srhdup + (sb) + 8 * (kk));     \
        ulonglong2 s1 = *(const ulonglong2*)(srhdup + (sb) + 8 * (kk) + 2); \
        ulonglong2 s2 = *(const ulonglong2*)(srhdup + (sb) + 8 * (kk) + 4); \
        ulonglong2 s3 = *(const ulonglong2*)(srhdup + (sb) + 8 * (kk) + 6); \
        fma2(ah0, uh0, s0.x); fma2(ah1, uh0, s0.y);                         \
        fma2(ah0, uh1, s1.x); fma2(ah1, uh1, s1.y);                         \
        fma2(ah0, uh2, s2.x); fma2(ah1, uh2, s2.y);                         \
        fma2(ah0, uh3, s3.x); fma2(ah1, uh3, s3.y);                         \
    }

__global__ void __launch_bounds__(512, 1) gru_scan9(const int* __restrict__ x)
{
    extern __shared__ __align__(16) char smraw[];
    uint4* pin_zr4 = (uint4*)smraw;                   // [64 k2-rows][128 jg] 131072 B
    uint4* pin_uh4 = (uint4*)(smraw + 131072);        // [32 k4-rows][128 jg]  65536 B
    ull*   hdup    = (ull*)(smraw + 196608);          // 520 ull, padded (+2 per 64-k)
    ull*   srhdup  = (ull*)(smraw + 200768);          // 520 ull, padded

    const int t    = threadIdx.x;
    const int lane = t & 31;
    const int w    = t >> 5;
    const int jp   = (w << 3) | (lane & 7);   // col-pair 0..127
    const int kh   = lane >> 3;               // 0..3
    const int row  = kh & 1;
    const int csel = kh >> 1;
    const int mycol = (jp << 1) | csel;
    const int b0   = blockIdx.x * 2;

    // ---- pin the FIRST k-half of every kh-quarter (all columns) ----
    // pin_zr4 row i (0..63) <-> global k2 = (i>>4)*32 + (i&15)
    for (int i = t; i < 64 * 128; i += 512) {
        int prow = i >> 7, jgc = i & 127;
        int gk2 = ((prow >> 4) << 5) + (prow & 15);
        pin_zr4[i] = g_zr4[gk2 * 128 + jgc];
    }
    // pin_uh4 row i (0..31) <-> global k4 = (i>>3)*16 + (i&7)
    for (int i = t; i < 32 * 128; i += 512) {
        int prow = i >> 7, jgc = i & 127;
        int gk4 = ((prow >> 3) << 4) + (prow & 7);
        pin_uh4[i] = g_uh4[gk4 * 128 + jgc];
    }
    for (int i = t; i < 520; i += 512) { hdup[i] = 0ULL; srhdup[i] = 0ULL; }
    __syncthreads();

    // per-warp-uniform stream bases
    const uint4* zsP = pin_zr4 + (kh * 16) * 128 + jp;        // smem, k2 = kh*32 + [0,16)
    const uint4* zgP = g_zr4   + (kh * 32 + 16) * 128 + jp;   // gmem, k2 = kh*32 + [16,32)
    const uint4* hsP = pin_uh4 + (kh * 8) * 128 + jp;         // smem, k4 = kh*16 + [0,8)
    const uint4* hgP = g_uh4   + (kh * 16 + 8) * 128 + jp;    // gmem, k4 = kh*16 + [8,16)
    const int hb = 130 * kh;   // padded ull base for this kh's 64-k block

    // global register rings (all warps; cross-step wraparound)
    uint4 zr_ring[8], uh_ring[4];
#pragma unroll
    for (int i = 0; i < 8; i++) zr_ring[i] = zgP[i * 128];
#pragma unroll
    for (int i = 0; i < 4; i++) uh_ring[i] = hgP[i * 128];

    // lane-owned state + e/token pipeline
    float hold = 0.0f, zg = 0.0f;
    const int xrow = (b0 + row) * SSZ;
    const int wc = 2 * mycol + row + ((mycol >> 6) << 1);   // padded state idx
    int tok = __ldg(&x[xrow]);
    const float* e0 = g_eproj + (size_t)tok * 768;
    float ez = __ldg(e0 + mycol);
    float er = __ldg(e0 + 256 + mycol);
    float eh = __ldg(e0 + 512 + mycol);
    int tok1 = __ldg(&x[xrow + 1]);

    for (int s = 0; s < SSZ; s++) {
        // ================= phase 1: z, r partials (64 k) =================
        ull az0 = 0, az1 = 0, ar0 = 0, ar1 = 0;
#pragma unroll
        for (int kk = 0; kk < 16; kk++) {                 // pinned half (LDS)
            uint4 u = zsP[kk * 128];
            P1BODY(u, hb, kk);
        }
#pragma unroll
        for (int kk = 0; kk < 16; kk++) {                 // global half (LDG ring)
            uint4 u = zr_ring[kk & 7];
            zr_ring[kk & 7] = zgP[((kk + 8) & 15) * 128];
            P1BODY(u, hb + 64, kk);
        }
        az0 = bflyadd(az0); az1 = bflyadd(az1);
        ar0 = bflyadd(ar0); ar1 = bflyadd(ar1);

        const float sz = pick(row ? az1 : az0, csel);
        const float sr = pick(row ? ar1 : ar0, csel);
        zg = fast_sigm(sz + ez);
        const float rg = fast_sigm(sr + er);
        const float rh = rg * hold;
        srhdup[wc] = pk2(rh, rh);
        // prefetch next step's z/r e-values + token s+2 (spread LDG issue)
        const float* en = g_eproj + (size_t)tok1 * 768;
        ez = __ldg(en + mycol);
        er = __ldg(en + 256 + mycol);
        const int s2 = (s + 2 < SSZ) ? s + 2 : SSZ - 1;
        const int tok2 = __ldg(&x[xrow + s2]);
        __syncthreads();

        // ================= phase 2: h_tilde partials (64 k) =================
        ull ah0 = 0, ah1 = 0;
#pragma unroll
        for (int kk = 0; kk < 8; kk++) {                  // pinned half (LDS)
            uint4 u = hsP[kk * 128];
            P2BODY(u, hb, kk);
        }
#pragma unroll
        for (int kk = 0; kk < 8; kk++) {                  // global half (LDG ring)
            uint4 u = uh_ring[kk & 3];
            uh_ring[kk & 3] = hgP[((kk + 4) & 7) * 128];
            P2BODY(u, hb + 64, kk);
        }
        ah0 = bflyadd(ah0); ah1 = bflyadd(ah1);

        const float sh = pick(row ? ah1 : ah0, csel);
        const float ht = fast_tanh(sh + eh);
        hold += zg * (ht - hold);
        hdup[wc] = pk2(hold, hold);
        eh = __ldg(en + 512 + mycol);
        tok1 = tok2;
        __syncthreads();
    }

    g_hlast[(size_t)(b0 + row) * HSZ + mycol] = hold;
}

// ============================================================================
extern "C" void kernel_launch(void* const* d_in, const int* in_sizes, int n_in,
                              void* d_out, int out_size)
{
    const int*   x   = (const int*)  d_in[0];
    const float* emb = (const float*)d_in[1];
    const float* Wz  = (const float*)d_in[2];
    const float* bz  = (const float*)d_in[3];
    const float* Uz  = (const float*)d_in[4];
    const float* buz = (const float*)d_in[5];
    const float* Wr  = (const float*)d_in[6];
    const float* br  = (const float*)d_in[7];
    const float* Ur  = (const float*)d_in[8];
    const float* bur = (const float*)d_in[9];
    const float* Wh  = (const float*)d_in[10];
    const float* bh  = (const float*)d_in[11];
    const float* Uh  = (const float*)d_in[12];
    const float* buh = (const float*)d_in[13];
    const float* Wf  = (const float*)d_in[14];
    const float* bf  = (const float*)d_in[15];
    float* out = (float*)d_out;

    float* eproj = nullptr;
    float* hlast = nullptr;
    cudaGetSymbolAddress((void**)&eproj, g_eproj);
    cudaGetSymbolAddress((void**)&hlast, g_hlast);

    cudaFuncSetAttribute(gru_scan9,
                         cudaFuncAttributeMaxDynamicSharedMemorySize, SCAN_SM_BYTES);

    dim3 blk(256);
    pack_u<<<128, 128>>>(Uz, Ur, Uh);
    sgemm_nt_bias<<<dim3(250, 2), blk>>>(emb, Wz, bz, buz, eproj, 768, 0);
    sgemm_nt_bias<<<dim3(250, 2), blk>>>(emb, Wr, br, bur, eproj, 768, 256);
    sgemm_nt_bias<<<dim3(250, 2), blk>>>(emb, Wh, bh, buh, eproj, 768, 512);

    gru_scan9<<<128, 512, SCAN_SM_BYTES>>>(x);

    sgemm_nt_bias<<<dim3(2, 250), blk>>>(hlast, Wf, bf, nullptr, out, 32000, 0);
}